// round 11
// baseline (speedup 1.0000x reference)
#include <cuda_runtime.h>

#define Bb     8
#define Nn     3136
#define Cc     64
#define CI     32
#define BNROWS 25088          // Bb * Nn
#define LAMF   0.1f
#define HSTEP  0.05f
#define BNEPS  1e-3f
#define INVN   (1.0f / 3136.0f)

// ---- scratch (static device globals; no allocation) ----
__device__ float d_theta[BNROWS * CI];
__device__ float d_phi[BNROWS * CI];
__device__ float d_phisum[Bb * CI];      // finalized inside k_apply<0>
__device__ float d_pspart[784 * CI];     // per-block phi-sum partials
__device__ float d_M[2][Bb * 2048];      // phi^T g per iter; zeroed by k_zero
__device__ float d_g1[BNROWS * Cc];

__device__ __forceinline__ void redg_v4(float* p, float a, float b, float c, float d) {
    asm volatile("red.global.add.v4.f32 [%0], {%1, %2, %3, %4};"
                 :: "l"(p), "f"(a), "f"(b), "f"(c), "f"(d) : "memory");
}

// ===========================================================================
// K0: zero both d_M buffers (stream-ordered before any REDG).
__global__ void k_zero() {
    int i = blockIdx.x * 256 + threadIdx.x;    // 16 * 256 = 4096
    float4 z = make_float4(0.f, 0.f, 0.f, 0.f);
    ((float4*)d_M)[i * 2]     = z;
    ((float4*)d_M)[i * 2 + 1] = z;
}

// ===========================================================================
// K1: theta/phi = x @ Wt/Wp + bias; per-block phi-sum partials; fused
// M0 += phi^T x partial via R9-pattern outer product + v4 REDG.
// 32 rows/block, grid 784.
__global__ void __launch_bounds__(256) k_front(
        const float* __restrict__ x,
        const float* __restrict__ Wt, const float* __restrict__ bt,
        const float* __restrict__ Wp, const float* __restrict__ bp) {
    __shared__ float sm[7456];
    float* SX   = sm;            // [32][64]          2048
    float* SWT  = sm + 2048;     // [32][68]          2176  (overlaid by partials)
    float* SWP  = sm + 4224;     // [32][68]          2176  (overlaid by partials)
    float* SPH  = sm + 6400;     // [32][32]          1024
    float* SP   = sm + 7424;     // 32
    float* PART = sm + 2048;     // [2][32][68] = 4352 overlay

    int t  = threadIdx.x;
    int gb = blockIdx.x;
    int b  = gb / 98;
    int r0 = gb * 32;

    {
        const float4* src = (const float4*)(x + r0 * 64);
        ((float4*)SX)[t]       = src[t];
        ((float4*)SX)[t + 256] = src[t + 256];
    }
    for (int e = t; e < 2048; e += 256) {   // weights transposed
        int k = e >> 5, d = e & 31;
        SWT[d * 68 + k] = Wt[e];
        SWP[d * 68 + k] = Wp[e];
    }
    if (t < 32) SP[t] = 0.f;
    __syncthreads();

    int w = t >> 5, d = t & 31;
    float th[4], ph[4];
    float bt_d = bt[d], bp_d = bp[d];
#pragma unroll
    for (int j = 0; j < 4; j++) { th[j] = bt_d; ph[j] = bp_d; }

    const float* xr = SX + w * 4 * 64;
    const float* wt = SWT + d * 68;
    const float* wp = SWP + d * 68;
#pragma unroll
    for (int k = 0; k < 64; k += 4) {
        float4 a = *(const float4*)(wt + k);
        float4 b2 = *(const float4*)(wp + k);
#pragma unroll
        for (int j = 0; j < 4; j++) {
            float4 xv = *(const float4*)(xr + j * 64 + k);
            th[j] = fmaf(xv.x, a.x, th[j]);  th[j] = fmaf(xv.y, a.y, th[j]);
            th[j] = fmaf(xv.z, a.z, th[j]);  th[j] = fmaf(xv.w, a.w, th[j]);
            ph[j] = fmaf(xv.x, b2.x, ph[j]); ph[j] = fmaf(xv.y, b2.y, ph[j]);
            ph[j] = fmaf(xv.z, b2.z, ph[j]); ph[j] = fmaf(xv.w, b2.w, ph[j]);
        }
    }
    int r = r0 + w * 4;
    float phs = 0.f;
#pragma unroll
    for (int j = 0; j < 4; j++) {
        d_theta[(r + j) * 32 + d] = th[j];
        d_phi[(r + j) * 32 + d]   = ph[j];
        SPH[(w * 4 + j) * 32 + d] = ph[j];
        phs += ph[j];
    }
    atomicAdd(&SP[d], phs);
    __syncthreads();
    if (t < 32) d_pspart[gb * 32 + t] = SP[t];

    // ---- fused M0 partial: phi_chunk^T @ x_chunk (R9 pattern) ----
    int rg = t >> 7;              // 2 row groups of 16 rows
    int u  = t & 127;
    int d0 = (u >> 4) * 4;
    int c0 = (u & 15) * 4;

    float acc[4][4];
#pragma unroll
    for (int i = 0; i < 4; i++)
#pragma unroll
        for (int j = 0; j < 4; j++) acc[i][j] = 0.f;

    const float* P = SPH + rg * 16 * 32;
    const float* G = SX + rg * 16 * 64;
#pragma unroll 8
    for (int j = 0; j < 16; j++) {
        float4 p  = *(const float4*)(P + j * 32 + d0);
        float4 gv = *(const float4*)(G + j * 64 + c0);
        acc[0][0] = fmaf(p.x, gv.x, acc[0][0]); acc[0][1] = fmaf(p.x, gv.y, acc[0][1]);
        acc[0][2] = fmaf(p.x, gv.z, acc[0][2]); acc[0][3] = fmaf(p.x, gv.w, acc[0][3]);
        acc[1][0] = fmaf(p.y, gv.x, acc[1][0]); acc[1][1] = fmaf(p.y, gv.y, acc[1][1]);
        acc[1][2] = fmaf(p.y, gv.z, acc[1][2]); acc[1][3] = fmaf(p.y, gv.w, acc[1][3]);
        acc[2][0] = fmaf(p.z, gv.x, acc[2][0]); acc[2][1] = fmaf(p.z, gv.y, acc[2][1]);
        acc[2][2] = fmaf(p.z, gv.z, acc[2][2]); acc[2][3] = fmaf(p.z, gv.w, acc[2][3]);
        acc[3][0] = fmaf(p.w, gv.x, acc[3][0]); acc[3][1] = fmaf(p.w, gv.y, acc[3][1]);
        acc[3][2] = fmaf(p.w, gv.z, acc[3][2]); acc[3][3] = fmaf(p.w, gv.w, acc[3][3]);
    }
    __syncthreads();   // SWT/SWP reads done (GEMM) — safe to overlay partials

#pragma unroll
    for (int di = 0; di < 4; di++) {
        *(float4*)(PART + rg * 2176 + (d0 + di) * 68 + c0) =
            make_float4(acc[di][0], acc[di][1], acc[di][2], acc[di][3]);
    }
    __syncthreads();

    int dd = t >> 3, cc = (t & 7) * 8;
    const float* p0 = PART + dd * 68 + cc;
    float4 a0 = *(const float4*)(p0);
    float4 a1 = *(const float4*)(p0 + 4);
    float4 b0 = *(const float4*)(p0 + 2176);
    float4 b1 = *(const float4*)(p0 + 2176 + 4);
    float* Mb = d_M[0] + b * 2048 + dd * 64 + cc;
    redg_v4(Mb,     a0.x + b0.x, a0.y + b0.y, a0.z + b0.z, a0.w + b0.w);
    redg_v4(Mb + 4, a1.x + b1.x, a1.y + b1.y, a1.z + b1.z, a1.w + b1.w);
}

// ===========================================================================
// K2/K3: two-phase apply (R9-proven core).
//   phase1: raw = theta @ M (K=32); fg = (lam/N)*raw - (s/N)*g
//   phase2: o = fg @ W + bias; BN; ReLU; out = x + 0.05*o
// ITER==0: phisum computed in-block from d_pspart (chunk 0 publishes it),
//          and fused M1 += phi^T out partial (R9 pattern).
// ITER==1: phisum read from d_phisum.
template<int ITER>
__global__ void __launch_bounds__(256) k_apply(
        const float* __restrict__ x,
        const float* __restrict__ Wst, const float* __restrict__ bst,
        const float* __restrict__ gam, const float* __restrict__ bet,
        const float* __restrict__ mmean, const float* __restrict__ mvar,
        float* __restrict__ out_ext) {
    const float* gin = ITER ? d_g1 : x;
    float* out       = ITER ? out_ext : d_g1;

    __shared__ float sm[9056];
    float* sAt  = sm;          // theta^T [k=32][row 64] pad 68   (2176)
    float* sM   = sm + 2176;   // M [k=32][col 64] pad 68          (2176)
    float* sW   = sm + 4352;   // W [k=64][col 64] pad 68          (4352)
    float* sfgT = sm;          // fg^T overlay
    float* SOUT = sm;          // out tile [64][68] overlay (4352)
    float* SPHI = sm + 4352;   // phi chunk [64][32] overlay (2048)
    float* PART = sm;          // [2][32][68] overlay (4352)
    float* ss   = sm + 8704;   // 64
    float* sps  = sm + 8768;   // 32
    float* sred = sm + 8800;   // 256

    int t  = threadIdx.x;
    int r0 = blockIdx.x * 64;
    int b  = blockIdx.x / 49;
    int chunk = blockIdx.x % 49;

    // stage theta^T
#pragma unroll
    for (int j = 0; j < 2; j++) {
        int e = t + j * 256;
        int r = e >> 3, dd = (e & 7) * 4;
        float4 v = ((const float4*)(d_theta + r0 * 32))[e];
        sAt[(dd + 0) * 68 + r] = v.x;
        sAt[(dd + 1) * 68 + r] = v.y;
        sAt[(dd + 2) * 68 + r] = v.z;
        sAt[(dd + 3) * 68 + r] = v.w;
    }
    // stage M
    const float* Mi = d_M[ITER] + b * 2048;
#pragma unroll
    for (int j = 0; j < 2; j++) {
        int e = t + j * 256;
        int k = e >> 4, c4 = (e & 15) * 4;
        *(float4*)(sM + k * 68 + c4) = ((const float4*)Mi)[e];
    }
    // stage W
    const float* Wi = Wst + ITER * 4096;
#pragma unroll
    for (int j = 0; j < 4; j++) {
        int e = t + j * 256;
        int k = e >> 4, c4 = (e & 15) * 4;
        *(float4*)(sW + k * 68 + c4) = ((const float4*)Wi)[e];
    }
    // phisum
    if (ITER == 0) {
        int lane = t & 31, grp = t >> 5;
        float a = 0.f;
        for (int j = grp; j < 98; j += 8)
            a += d_pspart[(b * 98 + j) * 32 + lane];
        sred[grp * 32 + lane] = a;
    } else {
        if (t < 32) sps[t] = d_phisum[b * 32 + t];
    }
    __syncthreads();
    if (ITER == 0) {
        if (t < 32) {
            float a = 0.f;
#pragma unroll
            for (int g2 = 0; g2 < 8; g2++) a += sred[g2 * 32 + t];
            sps[t] = a;
            if (chunk == 0) d_phisum[b * 32 + t] = a;   // publish for apply<1>
        }
        __syncthreads();
    }

    if (t < 64) {   // -(s/N) per row, s = LAM * theta . phisum
        float a = 0.f;
#pragma unroll
        for (int k = 0; k < 32; k++) a = fmaf(sAt[k * 68 + t], sps[k], a);
        ss[t] = a * (-LAMF * INVN);
    }
    __syncthreads();

    int tx = t & 15, ty = t >> 4;
    int rr = ty * 4, cc = tx * 4;

    // ---- phase 1: raw = theta @ M (K=32) ----
    float fg[4][4];
#pragma unroll
    for (int i = 0; i < 4; i++)
#pragma unroll
        for (int j = 0; j < 4; j++) fg[i][j] = 0.f;

#pragma unroll 8
    for (int k = 0; k < 32; k++) {
        float4 a  = *(const float4*)(sAt + k * 68 + rr);
        float4 bv = *(const float4*)(sM + k * 68 + cc);
        fg[0][0] = fmaf(a.x, bv.x, fg[0][0]); fg[0][1] = fmaf(a.x, bv.y, fg[0][1]);
        fg[0][2] = fmaf(a.x, bv.z, fg[0][2]); fg[0][3] = fmaf(a.x, bv.w, fg[0][3]);
        fg[1][0] = fmaf(a.y, bv.x, fg[1][0]); fg[1][1] = fmaf(a.y, bv.y, fg[1][1]);
        fg[1][2] = fmaf(a.y, bv.z, fg[1][2]); fg[1][3] = fmaf(a.y, bv.w, fg[1][3]);
        fg[2][0] = fmaf(a.z, bv.x, fg[2][0]); fg[2][1] = fmaf(a.z, bv.y, fg[2][1]);
        fg[2][2] = fmaf(a.z, bv.z, fg[2][2]); fg[2][3] = fmaf(a.z, bv.w, fg[2][3]);
        fg[3][0] = fmaf(a.w, bv.x, fg[3][0]); fg[3][1] = fmaf(a.w, bv.y, fg[3][1]);
        fg[3][2] = fmaf(a.w, bv.z, fg[3][2]); fg[3][3] = fmaf(a.w, bv.w, fg[3][3]);
    }
    const float c1 = LAMF * INVN;
#pragma unroll
    for (int i = 0; i < 4; i++) {
        float sneg = ss[rr + i];
        float4 gv = *(const float4*)(gin + (r0 + rr + i) * 64 + cc);
        fg[i][0] = fmaf(sneg, gv.x, c1 * fg[i][0]);
        fg[i][1] = fmaf(sneg, gv.y, c1 * fg[i][1]);
        fg[i][2] = fmaf(sneg, gv.z, c1 * fg[i][2]);
        fg[i][3] = fmaf(sneg, gv.w, c1 * fg[i][3]);
    }
    __syncthreads();   // sAt/sM fully read; reuse as sfgT

    // store fg transposed: sfgT[k=col][row]
#pragma unroll
    for (int j = 0; j < 4; j++) {
        float4 v = make_float4(fg[0][j], fg[1][j], fg[2][j], fg[3][j]);
        *(float4*)(sfgT + (cc + j) * 68 + rr) = v;
    }
    __syncthreads();

    // ---- phase 2: o = fg @ W (K=64) ----
    float acc[4][4];
#pragma unroll
    for (int i = 0; i < 4; i++)
#pragma unroll
        for (int j = 0; j < 4; j++) acc[i][j] = 0.f;

#pragma unroll 8
    for (int k = 0; k < 64; k++) {
        float4 a  = *(const float4*)(sfgT + k * 68 + rr);
        float4 bv = *(const float4*)(sW + k * 68 + cc);
        acc[0][0] = fmaf(a.x, bv.x, acc[0][0]); acc[0][1] = fmaf(a.x, bv.y, acc[0][1]);
        acc[0][2] = fmaf(a.x, bv.z, acc[0][2]); acc[0][3] = fmaf(a.x, bv.w, acc[0][3]);
        acc[1][0] = fmaf(a.y, bv.x, acc[1][0]); acc[1][1] = fmaf(a.y, bv.y, acc[1][1]);
        acc[1][2] = fmaf(a.y, bv.z, acc[1][2]); acc[1][3] = fmaf(a.y, bv.w, acc[1][3]);
        acc[2][0] = fmaf(a.z, bv.x, acc[2][0]); acc[2][1] = fmaf(a.z, bv.y, acc[2][1]);
        acc[2][2] = fmaf(a.z, bv.z, acc[2][2]); acc[2][3] = fmaf(a.z, bv.w, acc[2][3]);
        acc[3][0] = fmaf(a.w, bv.x, acc[3][0]); acc[3][1] = fmaf(a.w, bv.y, acc[3][1]);
        acc[3][2] = fmaf(a.w, bv.z, acc[3][2]); acc[3][3] = fmaf(a.w, bv.w, acc[3][3]);
    }
    if (ITER == 0) __syncthreads();   // sfgT/sW dead before overlay

    // epilogue: bias, BN, ReLU, residual (last == x always)
    float4 bias = *(const float4*)(bst + ITER * 64 + cc);
    float4 gm   = *(const float4*)(gam + ITER * 64 + cc);
    float4 bt4  = *(const float4*)(bet + ITER * 64 + cc);
    float4 mmv  = *(const float4*)(mmean + ITER * 64 + cc);
    float4 mv   = *(const float4*)(mvar + ITER * 64 + cc);
    float scl[4]  = { gm.x * rsqrtf(mv.x + BNEPS), gm.y * rsqrtf(mv.y + BNEPS),
                      gm.z * rsqrtf(mv.z + BNEPS), gm.w * rsqrtf(mv.w + BNEPS) };
    float bia[4]  = { bias.x, bias.y, bias.z, bias.w };
    float mean[4] = { mmv.x, mmv.y, mmv.z, mmv.w };
    float betc[4] = { bt4.x, bt4.y, bt4.z, bt4.w };

#pragma unroll
    for (int i = 0; i < 4; i++) {
        int r = r0 + rr + i;
        float4 xv = *(const float4*)(x + r * 64 + cc);
        float xa[4] = { xv.x, xv.y, xv.z, xv.w };
        float4 ov;
        float* op = (float*)&ov;
#pragma unroll
        for (int j = 0; j < 4; j++) {
            float o = acc[i][j] + bia[j];
            o = (o - mean[j]) * scl[j] + betc[j];
            o = fmaxf(o, 0.f);
            op[j] = xa[j] + HSTEP * o;
        }
        *(float4*)(out + r * 64 + cc) = ov;
        if (ITER == 0) *(float4*)(SOUT + (rr + i) * 68 + cc) = ov;
    }

    if (ITER == 0) {
        // stage phi chunk [row][d]
        const float4* psrc = (const float4*)(d_phi + r0 * 32);
        ((float4*)SPHI)[t]       = psrc[t];
        ((float4*)SPHI)[t + 256] = psrc[t + 256];
        __syncthreads();

        // fused M1 partial: phi_chunk^T @ out_chunk (R9 pattern)
        int rg = t >> 7;
        int u  = t & 127;
        int d0 = (u >> 4) * 4;
        int c0 = (u & 15) * 4;
        float ma[4][4];
#pragma unroll
        for (int i = 0; i < 4; i++)
#pragma unroll
            for (int j = 0; j < 4; j++) ma[i][j] = 0.f;

        const float* P = SPHI + rg * 32 * 32;
        const float* G = SOUT + rg * 32 * 68;
#pragma unroll 8
        for (int j = 0; j < 32; j++) {
            float4 p  = *(const float4*)(P + j * 32 + d0);
            float4 gv = *(const float4*)(G + j * 68 + c0);
            ma[0][0] = fmaf(p.x, gv.x, ma[0][0]); ma[0][1] = fmaf(p.x, gv.y, ma[0][1]);
            ma[0][2] = fmaf(p.x, gv.z, ma[0][2]); ma[0][3] = fmaf(p.x, gv.w, ma[0][3]);
            ma[1][0] = fmaf(p.y, gv.x, ma[1][0]); ma[1][1] = fmaf(p.y, gv.y, ma[1][1]);
            ma[1][2] = fmaf(p.y, gv.z, ma[1][2]); ma[1][3] = fmaf(p.y, gv.w, ma[1][3]);
            ma[2][0] = fmaf(p.z, gv.x, ma[2][0]); ma[2][1] = fmaf(p.z, gv.y, ma[2][1]);
            ma[2][2] = fmaf(p.z, gv.z, ma[2][2]); ma[2][3] = fmaf(p.z, gv.w, ma[2][3]);
            ma[3][0] = fmaf(p.w, gv.x, ma[3][0]); ma[3][1] = fmaf(p.w, gv.y, ma[3][1]);
            ma[3][2] = fmaf(p.w, gv.z, ma[3][2]); ma[3][3] = fmaf(p.w, gv.w, ma[3][3]);
        }
        __syncthreads();   // SOUT/SPHI reads done — safe to overlay PART

#pragma unroll
        for (int di = 0; di < 4; di++) {
            *(float4*)(PART + rg * 2176 + (d0 + di) * 68 + c0) =
                make_float4(ma[di][0], ma[di][1], ma[di][2], ma[di][3]);
        }
        __syncthreads();

        int dd = t >> 3, cc2 = (t & 7) * 8;
        const float* p0 = PART + dd * 68 + cc2;
        float4 a0 = *(const float4*)(p0);
        float4 a1 = *(const float4*)(p0 + 4);
        float4 b0 = *(const float4*)(p0 + 2176);
        float4 b1 = *(const float4*)(p0 + 2176 + 4);
        float* Mb = d_M[1] + b * 2048 + dd * 64 + cc2;
        redg_v4(Mb,     a0.x + b0.x, a0.y + b0.y, a0.z + b0.z, a0.w + b0.w);
        redg_v4(Mb + 4, a1.x + b1.x, a1.y + b1.y, a1.z + b1.z, a1.w + b1.w);
    }
}

// ---------------------------------------------------------------------------
extern "C" void kernel_launch(void* const* d_in, const int* in_sizes, int n_in,
                              void* d_out, int out_size) {
    const float* x     = (const float*)d_in[0];
    const float* Wt    = (const float*)d_in[1];
    const float* bt    = (const float*)d_in[2];
    const float* Wp    = (const float*)d_in[3];
    const float* bp    = (const float*)d_in[4];
    const float* Wst   = (const float*)d_in[5];
    const float* bst   = (const float*)d_in[6];
    const float* gam   = (const float*)d_in[7];
    const float* bet   = (const float*)d_in[8];
    const float* mmean = (const float*)d_in[9];
    const float* mvar  = (const float*)d_in[10];
    float* out = (float*)d_out;

    k_zero<<<16, 256>>>();
    k_front<<<BNROWS / 32, 256>>>(x, Wt, bt, Wp, bp);
    k_apply<0><<<BNROWS / 64, 256>>>(x, Wst, bst, gam, bet, mmean, mvar, out);
    k_apply<1><<<BNROWS / 64, 256>>>(x, Wst, bst, gam, bet, mmean, mvar, out);
}